// round 10
// baseline (speedup 1.0000x reference)
#include <cuda_runtime.h>
#include <cuda_bf16.h>
#include <math.h>
#include <stdint.h>

#define B_ROWS 32768
#define OBS    512
#define H1D    1024
#define H2D    1024
#define ACT    64
#define NOUT   (2*ACT)

// ---------------- device scratch (static: no allocations allowed) ----------------
__device__ __nv_bfloat16 g_W1r[H1D*OBS];     // integer-valued bf16 weights (exact)
__device__ __nv_bfloat16 g_W2r[H2D*H1D];
__device__ __nv_bfloat16 g_W3r[NOUT*H2D];
__device__ float g_b1q[H1D];
__device__ float g_b2q[H2D];
__device__ float g_b3q[NOUT];
__device__ float g_scales[3];
__device__ unsigned g_maxbits[3] = {0u, 0u, 0u};   // atomicMax over identical data: idempotent
__device__ __nv_bfloat16 g_x[(size_t)B_ROWS*OBS];
__device__ __nv_bfloat16 g_h1[(size_t)B_ROWS*H1D];
__device__ __nv_bfloat16 g_h2[(size_t)B_ROWS*H2D];

// ---------------- PTX helpers (sm_103-safe subset only) ----------------
__device__ __forceinline__ uint32_t smem_u32(const void* p) {
    uint32_t a;
    asm("{ .reg .u64 t; cvta.to.shared.u64 t, %1; cvt.u32.u64 %0, t; }" : "=r"(a) : "l"(p));
    return a;
}
__device__ __forceinline__ void cpasync16(uint32_t dst, const void* src) {
    asm volatile("cp.async.cg.shared.global [%0], [%1], 16;" :: "r"(dst), "l"(src));
}
__device__ __forceinline__ void cp_commit() { asm volatile("cp.async.commit_group;" ::: "memory"); }
__device__ __forceinline__ void cp_wait1()  { asm volatile("cp.async.wait_group 1;" ::: "memory"); }
__device__ __forceinline__ void cp_wait0()  { asm volatile("cp.async.wait_group 0;" ::: "memory"); }

#define LDSM_X4(r0, r1, r2, r3, addr)                                          \
    asm volatile("ldmatrix.sync.aligned.m8n8.x4.shared.b16 {%0,%1,%2,%3}, [%4];" \
        : "=r"(r0), "=r"(r1), "=r"(r2), "=r"(r3) : "r"(addr))

#define MMA16816(c, a0, a1, a2, a3, b0, b1)                                    \
    asm volatile("mma.sync.aligned.m16n8k16.row.col.f32.bf16.bf16.f32 "        \
        "{%0,%1,%2,%3}, {%4,%5,%6,%7}, {%8,%9}, {%0,%1,%2,%3};"                \
        : "+f"((c)[0]), "+f"((c)[1]), "+f"((c)[2]), "+f"((c)[3])               \
        : "r"(a0), "r"(a1), "r"(a2), "r"(a3), "r"(b0), "r"(b1))

// ---------------- quantization prep ----------------
// fused 3-tensor max|W|: blocks [0,128)->W1, [128,384)->W2, [384,416)->W3
__global__ void maxabs3_kernel(const float* __restrict__ W1, const float* __restrict__ W2,
                               const float* __restrict__ W3) {
    const float* W; int n, slot, idx, nb;
    int b = blockIdx.x;
    if (b < 128)      { W = W1; n = H1D*OBS;  slot = 0; idx = b;       nb = 128; }
    else if (b < 384) { W = W2; n = H2D*H1D;  slot = 1; idx = b - 128; nb = 256; }
    else              { W = W3; n = NOUT*H2D; slot = 2; idx = b - 384; nb = 32;  }
    unsigned m = 0u;
    for (int i = idx*blockDim.x + threadIdx.x; i < n; i += nb*blockDim.x)
        m = max(m, __float_as_uint(fabsf(W[i])));
    #pragma unroll
    for (int o = 16; o; o >>= 1) m = max(m, __shfl_xor_sync(0xffffffffu, m, o));
    __shared__ unsigned sm[32];
    int lane = threadIdx.x & 31, wid = threadIdx.x >> 5;
    if (lane == 0) sm[wid] = m;
    __syncthreads();
    if (wid == 0) {
        m = (lane < (int)(blockDim.x >> 5)) ? sm[lane] : 0u;
        #pragma unroll
        for (int o = 16; o; o >>= 1) m = max(m, __shfl_xor_sync(0xffffffffu, m, o));
        if (lane == 0) atomicMax(&g_maxbits[slot], m);
    }
}

__device__ __forceinline__ float qwr(float w, float rs) {   // integer part (mult by recip; damped)
    float r = rintf(w * rs);
    return fminf(fmaxf(r, -127.0f), 127.0f);
}
__device__ __forceinline__ float qb(float b, float s, float rs) {
    float r = rintf(b * rs);
    r = fminf(fmaxf(r, -128.0f), 127.0f);
    return r * s;
}

__global__ void quant_all_kernel(const float* __restrict__ W1, const float* __restrict__ b1,
                                 const float* __restrict__ W2, const float* __restrict__ b2,
                                 const float* __restrict__ W3, const float* __restrict__ b3,
                                 float s_in) {
    const float ws1 = __fdiv_rn(__uint_as_float(g_maxbits[0]), 127.0f);
    const float ws2 = __fdiv_rn(__uint_as_float(g_maxbits[1]), 127.0f);
    const float ws3 = __fdiv_rn(__uint_as_float(g_maxbits[2]), 127.0f);
    const float rs1 = 1.0f / ws1, rs2 = 1.0f / ws2, rs3 = 1.0f / ws3;
    const float sb1 = s_in * ws1;
    const float sb2 = sb1 * ws2;
    const float sb3 = sb2 * ws3;
    const int tid = blockIdx.x*blockDim.x + threadIdx.x;
    const int stride = gridDim.x*blockDim.x;
    if (tid == 0) { g_scales[0] = ws1; g_scales[1] = ws2; g_scales[2] = ws3; }
    for (int i = tid; i < H1D*OBS/2; i += stride) {
        float2 v = ((const float2*)W1)[i];
        __nv_bfloat162 p;
        p.x = __float2bfloat16(qwr(v.x, rs1)); p.y = __float2bfloat16(qwr(v.y, rs1));
        ((__nv_bfloat162*)g_W1r)[i] = p;
    }
    for (int i = tid; i < H2D*H1D/2; i += stride) {
        float2 v = ((const float2*)W2)[i];
        __nv_bfloat162 p;
        p.x = __float2bfloat16(qwr(v.x, rs2)); p.y = __float2bfloat16(qwr(v.y, rs2));
        ((__nv_bfloat162*)g_W2r)[i] = p;
    }
    for (int i = tid; i < NOUT*H2D/2; i += stride) {
        float2 v = ((const float2*)W3)[i];
        __nv_bfloat162 p;
        p.x = __float2bfloat16(qwr(v.x, rs3)); p.y = __float2bfloat16(qwr(v.y, rs3));
        ((__nv_bfloat162*)g_W3r)[i] = p;
    }
    for (int i = tid; i < H1D;  i += stride) g_b1q[i] = qb(b1[i], sb1, 1.0f/sb1);
    for (int i = tid; i < H2D;  i += stride) g_b2q[i] = qb(b2[i], sb2, 1.0f/sb2);
    for (int i = tid; i < NOUT; i += stride) g_b3q[i] = qb(b3[i], sb3, 1.0f/sb3);
}

// ---------------- input conversion: x = obs * s_in^2 as bf16 (float4 -> bf16x4) ----------------
__global__ void conv_x_kernel(const float* __restrict__ obs) {
    const float F0 = (float)((1.0/12000.0) * (1.0/12000.0));
    const size_t n4 = (size_t)B_ROWS * OBS / 4;
    for (size_t i = (size_t)blockIdx.x*blockDim.x + threadIdx.x; i < n4;
         i += (size_t)gridDim.x*blockDim.x) {
        float4 v = ((const float4*)obs)[i];
        __nv_bfloat162 p0, p1;
        p0.x = __float2bfloat16(v.x * F0); p0.y = __float2bfloat16(v.y * F0);
        p1.x = __float2bfloat16(v.z * F0); p1.y = __float2bfloat16(v.w * F0);
        uint2 o; o.x = *(uint32_t*)&p0; o.y = *(uint32_t*)&p1;
        ((uint2*)g_x)[i] = o;
    }
}

// ---------------- HMMA GEMM, 256 threads (8 warps 2Mx4N), warp tile 64 x NTILE/4 ----------------
// D[128,NTILE] per CTA = A[M,K] @ Wr[N,K]^T. K in BK=64 chunks, 3-stage cp.async ring,
// ONE __syncthreads per chunk (wait -> sync -> load(i+2) -> compute).
// FUSED=false: epilogue *ws + bias + relu -> bf16 oH.
// FUSED=true (layer 3, NTILE=128=NOUT): stage net in smem, compute action+logp directly.
#define BK 64
#define ASTG (128*BK*2)          // 16 KB A per stage

template<int NTILE, bool FUSED>
__global__ __launch_bounds__(256, 1)
void gemm_mma(const __nv_bfloat16* __restrict__ A,
              const __nv_bfloat16* __restrict__ Br,  const float* __restrict__ bias,
              int K, int Nd, int sIdx,
              __nv_bfloat16* __restrict__ oH,
              const float* __restrict__ eps,
              float* __restrict__ outAction, float* __restrict__ outLogp) {
    constexpr int BSTG = NTILE * 128;           // B bytes per stage
    constexpr int STG  = ASTG + BSTG;
    constexpr int NT   = NTILE / 32;            // n-subtiles per warp (8 or 4)
    extern __shared__ __align__(128) char smem[];
    const uint32_t sb = smem_u32(smem);
    const int tid = threadIdx.x, wid = tid >> 5, lane = tid & 31;
    const int bm = blockIdx.y * 128, bn = blockIdx.x * NTILE;
    const int wm = wid >> 2, wn = wid & 3;      // 2 x 4 warps

    float acc[4][NT][4];
    #pragma unroll
    for (int i = 0; i < 4; i++)
        #pragma unroll
        for (int j = 0; j < NT; j++)
            #pragma unroll
            for (int v = 0; v < 4; v++) acc[i][j][v] = 0.0f;

    const int nIter = K >> 6;

    auto load_stage = [&](int i) {
        const uint32_t s0 = sb + (i % 3) * STG;
        const int k0 = i << 6;
        #pragma unroll
        for (int o = 0; o < 4; o++) {                   // A: 128 rows x 8 chunks
            int idx = tid + o * 256;
            int r = idx >> 3, c = idx & 7;
            uint32_t soff = (uint32_t)(r * 128 + ((c ^ (r & 7)) << 4));
            cpasync16(s0 + soff, A + (size_t)(bm + r) * K + k0 + c * 8);
        }
        #pragma unroll
        for (int o = 0; o < NTILE / 32; o++) {          // B: NTILE rows x 8 chunks
            int idx = tid + o * 256;
            int r = idx >> 3, c = idx & 7;
            cpasync16(s0 + ASTG + (uint32_t)(r * 128 + ((c ^ (r & 7)) << 4)),
                      Br + (size_t)(bn + r) * K + k0 + c * 8);
        }
        cp_commit();
    };

    // per-thread ldmatrix row/group decomposition (validated layout)
    const int g  = lane >> 3;
    const int glr = lane & 7;
    const int arow = (g & 1) * 8 + glr;   // A x4: rows pair then chunk pair
    const int ach  = g >> 1;
    const int brow = (g >> 1) * 8 + glr;  // B x4: chunk pair then rows pair
    const int bch  = g & 1;

    load_stage(0);
    load_stage(1);

    for (int i = 0; i < nIter; ++i) {
        if (i + 1 < nIter) cp_wait1();      // stage i arrived (i+1 may be in flight)
        else               cp_wait0();
        __syncthreads();                    // all warps done with compute(i-1); slot (i-1)%3 free
        if (i + 2 < nIter) load_stage(i + 2);

        const uint32_t s0 = sb + (i % 3) * STG;
        #pragma unroll
        for (int ks = 0; ks < 4; ks++) {
            const int c0 = ks * 2;
            uint32_t bf[NT][2];
            #pragma unroll
            for (int nt2 = 0; nt2 < NT / 2; nt2++) {
                int row = wn * (NTILE / 4) + nt2 * 16 + brow;
                uint32_t addr = s0 + ASTG + row * 128 + (((c0 + bch) ^ (row & 7)) << 4);
                LDSM_X4(bf[2*nt2][0], bf[2*nt2][1], bf[2*nt2+1][0], bf[2*nt2+1][1], addr);
            }
            uint32_t af[4][4];
            #pragma unroll
            for (int mt = 0; mt < 4; mt++) {
                int row = wm * 64 + mt * 16 + arow;
                uint32_t addr = s0 + row * 128 + (((c0 + ach) ^ (row & 7)) << 4);
                LDSM_X4(af[mt][0], af[mt][1], af[mt][2], af[mt][3], addr);
            }
            #pragma unroll
            for (int mt = 0; mt < 4; mt++)
                #pragma unroll
                for (int nt = 0; nt < NT; nt++)
                    MMA16816(acc[mt][nt], af[mt][0], af[mt][1], af[mt][2], af[mt][3],
                             bf[nt][0], bf[nt][1]);
        }
    }
    __syncthreads();

    // ---- epilogue ----
    const float ws = g_scales[sIdx];
    const int qr = lane >> 2;
    const int qc = (lane & 3) * 2;

    if (!FUSED) {
        #pragma unroll
        for (int mt = 0; mt < 4; mt++) {
            #pragma unroll
            for (int nt = 0; nt < NT; nt++) {
                int col = bn + wn * (NTILE / 4) + nt * 8 + qc;
                float bs0 = __ldg(&bias[col]), bs1 = __ldg(&bias[col + 1]);
                #pragma unroll
                for (int h = 0; h < 2; h++) {
                    size_t row = (size_t)(bm + wm * 64 + mt * 16 + qr + h * 8);
                    float o0 = fmaf(acc[mt][nt][2*h + 0], ws, bs0);
                    float o1 = fmaf(acc[mt][nt][2*h + 1], ws, bs1);
                    __nv_bfloat162 p;
                    p.x = __float2bfloat16(fmaxf(o0, 0.0f));
                    p.y = __float2bfloat16(fmaxf(o1, 0.0f));
                    *reinterpret_cast<__nv_bfloat162*>(oH + row * Nd + col) = p;
                }
            }
        }
    } else {
        // stage scaled net rows into smem: snet[128][128] (64 KB, fits 96 KB pipeline smem)
        float* snet = reinterpret_cast<float*>(smem);
        #pragma unroll
        for (int mt = 0; mt < 4; mt++) {
            #pragma unroll
            for (int nt = 0; nt < NT; nt++) {
                int col = wn * (NTILE / 4) + nt * 8 + qc;
                float bs0 = __ldg(&bias[col]), bs1 = __ldg(&bias[col + 1]);
                #pragma unroll
                for (int h = 0; h < 2; h++) {
                    int row = wm * 64 + mt * 16 + qr + h * 8;
                    snet[row * 128 + col]     = fmaf(acc[mt][nt][2*h + 0], ws, bs0);
                    snet[row * 128 + col + 1] = fmaf(acc[mt][nt][2*h + 1], ws, bs1);
                }
            }
        }
        __syncthreads();
        // distribution: each of 8 warps handles 16 rows
        #pragma unroll
        for (int rr = 0; rr < 16; rr++) {
            int row = wid * 16 + rr;
            size_t grow = (size_t)(bm + row);
            float s = 0.0f;
            #pragma unroll
            for (int h = 0; h < 2; h++) {
                int j = lane + h * 32;
                float mu = snet[row * 128 + j];
                float ls = fminf(fmaxf(snet[row * 128 + ACT + j], -20.0f), 2.0f);
                float sd = expf(ls);
                float e  = eps[grow * ACT + j];
                float pi = fmaf(sd, e, mu);
                outAction[grow * ACT + j] = tanhf(pi);
                float z  = (pi - mu) / sd;
                float m2p = -2.0f * pi;
                float sp  = fmaxf(m2p, 0.0f) + log1pf(expf(-fabsf(m2p)));  // softplus(-2*pi)
                s += -0.5f*z*z - ls - 0.91893853320467274f
                     - 2.0f*(0.69314718055994531f - pi - sp);
            }
            #pragma unroll
            for (int o = 16; o; o >>= 1) s += __shfl_xor_sync(0xffffffffu, s, o);
            if (lane == 0 && outLogp) outLogp[grow] = s;
        }
    }
}

// ---------------- launcher ----------------
extern "C" void kernel_launch(void* const* d_in, const int* in_sizes, int n_in,
                              void* d_out, int out_size) {
    const float* obs = (const float*)d_in[0];
    const float* eps = (const float*)d_in[1];
    const float* W1  = (const float*)d_in[2];
    const float* b1  = (const float*)d_in[3];
    const float* W2  = (const float*)d_in[4];
    const float* b2  = (const float*)d_in[5];
    const float* W3  = (const float*)d_in[6];
    const float* b3  = (const float*)d_in[7];

    float* out = (float*)d_out;
    float* outAction = out;
    float* outLogp = (out_size >= B_ROWS*(ACT+1)) ? (out + (size_t)B_ROWS*ACT) : nullptr;

    const float S_IN = (float)(1.0/12000.0);

    __nv_bfloat16 *pW1r, *pW2r, *pW3r, *px, *ph1, *ph2;
    float *pb1q, *pb2q, *pb3q;
    cudaGetSymbolAddress((void**)&pW1r, g_W1r);
    cudaGetSymbolAddress((void**)&pW2r, g_W2r);
    cudaGetSymbolAddress((void**)&pW3r, g_W3r);
    cudaGetSymbolAddress((void**)&pb1q, g_b1q);
    cudaGetSymbolAddress((void**)&pb2q, g_b2q);
    cudaGetSymbolAddress((void**)&pb3q, g_b3q);
    cudaGetSymbolAddress((void**)&px,  g_x);
    cudaGetSymbolAddress((void**)&ph1, g_h1);
    cudaGetSymbolAddress((void**)&ph2, g_h2);

    const int SMEM256 = 3 * (ASTG + 256*128);   // 147456
    const int SMEM128 = 3 * (ASTG + 128*128);   //  98304 (>= 64KB snet)
    cudaFuncSetAttribute(gemm_mma<256, false>, cudaFuncAttributeMaxDynamicSharedMemorySize, SMEM256);
    cudaFuncSetAttribute(gemm_mma<128, true>,  cudaFuncAttributeMaxDynamicSharedMemorySize, SMEM128);

    // 1) quantization prep (maxbits accumulates idempotently across replays)
    maxabs3_kernel<<<416, 256>>>(W1, W2, W3);
    quant_all_kernel<<<512, 256>>>(W1, b1, W2, b2, W3, b3, S_IN);

    // 2) input conversion
    conv_x_kernel<<<1024, 256>>>(obs);

    // 3) MLP on tensor cores (register HMMA, 8 warps/CTA)
    dim3 g1(H1D/256, B_ROWS/128);
    gemm_mma<256, false><<<g1, 256, SMEM256>>>(px, pW1r, pb1q, OBS, H1D, 0, ph1,
                                               nullptr, nullptr, nullptr);
    dim3 g2(H2D/256, B_ROWS/128);
    gemm_mma<256, false><<<g2, 256, SMEM256>>>(ph1, pW2r, pb2q, H1D, H2D, 1, ph2,
                                               nullptr, nullptr, nullptr);
    dim3 g3(1, B_ROWS/128);
    gemm_mma<128, true><<<g3, 256, SMEM128>>>(ph2, pW3r, pb3q, H2D, NOUT, 2, nullptr,
                                              eps, outAction, outLogp);
}

// round 11
// speedup vs baseline: 1.1452x; 1.1452x over previous
#include <cuda_runtime.h>
#include <cuda_bf16.h>
#include <math.h>
#include <stdint.h>

#define B_ROWS 32768
#define OBS    512
#define H1D    1024
#define H2D    1024
#define ACT    64
#define NOUT   (2*ACT)

// ---------------- device scratch (static: no allocations allowed) ----------------
__device__ __nv_bfloat16 g_W1r[H1D*OBS];     // integer-valued bf16 weights (exact)
__device__ __nv_bfloat16 g_W2r[H2D*H1D];
__device__ __nv_bfloat16 g_W3r[NOUT*H2D];
__device__ float g_b1q[H1D];
__device__ float g_b2q[H2D];
__device__ float g_b3q[NOUT];
__device__ float g_scales[3];
__device__ unsigned g_maxbits[3] = {0u, 0u, 0u};   // atomicMax over identical data: idempotent
__device__ __nv_bfloat16 g_x[(size_t)B_ROWS*OBS];
__device__ __nv_bfloat16 g_h1[(size_t)B_ROWS*H1D];
__device__ __nv_bfloat16 g_h2[(size_t)B_ROWS*H2D];

// ---------------- PTX helpers (sm_103-safe subset only) ----------------
__device__ __forceinline__ uint32_t smem_u32(const void* p) {
    uint32_t a;
    asm("{ .reg .u64 t; cvta.to.shared.u64 t, %1; cvt.u32.u64 %0, t; }" : "=r"(a) : "l"(p));
    return a;
}
__device__ __forceinline__ void cpasync16(uint32_t dst, const void* src) {
    asm volatile("cp.async.cg.shared.global [%0], [%1], 16;" :: "r"(dst), "l"(src));
}
__device__ __forceinline__ void cp_commit() { asm volatile("cp.async.commit_group;" ::: "memory"); }
__device__ __forceinline__ void cp_wait1()  { asm volatile("cp.async.wait_group 1;" ::: "memory"); }
__device__ __forceinline__ void cp_wait0()  { asm volatile("cp.async.wait_group 0;" ::: "memory"); }

#define LDSM_X4(r0, r1, r2, r3, addr)                                          \
    asm volatile("ldmatrix.sync.aligned.m8n8.x4.shared.b16 {%0,%1,%2,%3}, [%4];" \
        : "=r"(r0), "=r"(r1), "=r"(r2), "=r"(r3) : "r"(addr))

#define MMA16816(c, a0, a1, a2, a3, b0, b1)                                    \
    asm volatile("mma.sync.aligned.m16n8k16.row.col.f32.bf16.bf16.f32 "        \
        "{%0,%1,%2,%3}, {%4,%5,%6,%7}, {%8,%9}, {%0,%1,%2,%3};"                \
        : "+f"((c)[0]), "+f"((c)[1]), "+f"((c)[2]), "+f"((c)[3])               \
        : "r"(a0), "r"(a1), "r"(a2), "r"(a3), "r"(b0), "r"(b1))

// ---------------- quantization prep ----------------
// fused 3-tensor max|W|: blocks [0,128)->W1, [128,384)->W2, [384,416)->W3
__global__ void maxabs3_kernel(const float* __restrict__ W1, const float* __restrict__ W2,
                               const float* __restrict__ W3) {
    const float* W; int n, slot, idx, nb;
    int b = blockIdx.x;
    if (b < 128)      { W = W1; n = H1D*OBS;  slot = 0; idx = b;       nb = 128; }
    else if (b < 384) { W = W2; n = H2D*H1D;  slot = 1; idx = b - 128; nb = 256; }
    else              { W = W3; n = NOUT*H2D; slot = 2; idx = b - 384; nb = 32;  }
    unsigned m = 0u;
    for (int i = idx*blockDim.x + threadIdx.x; i < n; i += nb*blockDim.x)
        m = max(m, __float_as_uint(fabsf(W[i])));
    #pragma unroll
    for (int o = 16; o; o >>= 1) m = max(m, __shfl_xor_sync(0xffffffffu, m, o));
    __shared__ unsigned sm[32];
    int lane = threadIdx.x & 31, wid = threadIdx.x >> 5;
    if (lane == 0) sm[wid] = m;
    __syncthreads();
    if (wid == 0) {
        m = (lane < (int)(blockDim.x >> 5)) ? sm[lane] : 0u;
        #pragma unroll
        for (int o = 16; o; o >>= 1) m = max(m, __shfl_xor_sync(0xffffffffu, m, o));
        if (lane == 0) atomicMax(&g_maxbits[slot], m);
    }
}

__device__ __forceinline__ float qwr(float w, float rs) {   // integer part (mult by recip; damped)
    float r = rintf(w * rs);
    return fminf(fmaxf(r, -127.0f), 127.0f);
}
__device__ __forceinline__ float qb(float b, float s, float rs) {
    float r = rintf(b * rs);
    r = fminf(fmaxf(r, -128.0f), 127.0f);
    return r * s;
}

__global__ void quant_all_kernel(const float* __restrict__ W1, const float* __restrict__ b1,
                                 const float* __restrict__ W2, const float* __restrict__ b2,
                                 const float* __restrict__ W3, const float* __restrict__ b3,
                                 float s_in) {
    const float ws1 = __fdiv_rn(__uint_as_float(g_maxbits[0]), 127.0f);
    const float ws2 = __fdiv_rn(__uint_as_float(g_maxbits[1]), 127.0f);
    const float ws3 = __fdiv_rn(__uint_as_float(g_maxbits[2]), 127.0f);
    const float rs1 = 1.0f / ws1, rs2 = 1.0f / ws2, rs3 = 1.0f / ws3;
    const float sb1 = s_in * ws1;
    const float sb2 = sb1 * ws2;
    const float sb3 = sb2 * ws3;
    const int tid = blockIdx.x*blockDim.x + threadIdx.x;
    const int stride = gridDim.x*blockDim.x;
    if (tid == 0) { g_scales[0] = ws1; g_scales[1] = ws2; g_scales[2] = ws3; }
    for (int i = tid; i < H1D*OBS/2; i += stride) {
        float2 v = ((const float2*)W1)[i];
        __nv_bfloat162 p;
        p.x = __float2bfloat16(qwr(v.x, rs1)); p.y = __float2bfloat16(qwr(v.y, rs1));
        ((__nv_bfloat162*)g_W1r)[i] = p;
    }
    for (int i = tid; i < H2D*H1D/2; i += stride) {
        float2 v = ((const float2*)W2)[i];
        __nv_bfloat162 p;
        p.x = __float2bfloat16(qwr(v.x, rs2)); p.y = __float2bfloat16(qwr(v.y, rs2));
        ((__nv_bfloat162*)g_W2r)[i] = p;
    }
    for (int i = tid; i < NOUT*H2D/2; i += stride) {
        float2 v = ((const float2*)W3)[i];
        __nv_bfloat162 p;
        p.x = __float2bfloat16(qwr(v.x, rs3)); p.y = __float2bfloat16(qwr(v.y, rs3));
        ((__nv_bfloat162*)g_W3r)[i] = p;
    }
    for (int i = tid; i < H1D;  i += stride) g_b1q[i] = qb(b1[i], sb1, 1.0f/sb1);
    for (int i = tid; i < H2D;  i += stride) g_b2q[i] = qb(b2[i], sb2, 1.0f/sb2);
    for (int i = tid; i < NOUT; i += stride) g_b3q[i] = qb(b3[i], sb3, 1.0f/sb3);
}

// ---------------- input conversion: x = obs * s_in^2 as bf16 (float4 -> bf16x4) ----------------
__global__ void conv_x_kernel(const float* __restrict__ obs) {
    const float F0 = (float)((1.0/12000.0) * (1.0/12000.0));
    const size_t n4 = (size_t)B_ROWS * OBS / 4;
    for (size_t i = (size_t)blockIdx.x*blockDim.x + threadIdx.x; i < n4;
         i += (size_t)gridDim.x*blockDim.x) {
        float4 v = ((const float4*)obs)[i];
        __nv_bfloat162 p0, p1;
        p0.x = __float2bfloat16(v.x * F0); p0.y = __float2bfloat16(v.y * F0);
        p1.x = __float2bfloat16(v.z * F0); p1.y = __float2bfloat16(v.w * F0);
        uint2 o; o.x = *(uint32_t*)&p0; o.y = *(uint32_t*)&p1;
        ((uint2*)g_x)[i] = o;
    }
}

// ---------------- HMMA GEMM, 128x128 CTA tile, 2 CTAs/SM ----------------
// 8 warps (2M x 4N), warp tile 64x32 -> acc 64 regs/thread; <=124 regs total so
// TWO CTAs co-reside per SM (16 warps/SM, independent barriers -> tensor pipe
// stays fed across sync/cp-wait boundaries).
// K in BK=64 chunks, 3-stage cp.async ring, one __syncthreads per chunk.
// FUSED=false: epilogue *ws + bias + relu -> bf16 oH.
// FUSED=true (layer 3): stage net in smem, compute action+logp directly.
#define BK 64
#define ASTG (128*BK*2)          // 16 KB A per stage
#define BSTG (128*BK*2)          // 16 KB B per stage (NTILE=128)
#define STG  (ASTG + BSTG)       // 32 KB per stage; 3 stages = 96 KB

template<bool FUSED>
__global__ __launch_bounds__(256, 2)
void gemm_mma(const __nv_bfloat16* __restrict__ A,
              const __nv_bfloat16* __restrict__ Br,  const float* __restrict__ bias,
              int K, int Nd, int sIdx,
              __nv_bfloat16* __restrict__ oH,
              const float* __restrict__ eps,
              float* __restrict__ outAction, float* __restrict__ outLogp) {
    constexpr int NT = 4;                       // n-subtiles per warp (32 cols)
    extern __shared__ __align__(128) char smem[];
    const uint32_t sb = smem_u32(smem);
    const int tid = threadIdx.x, wid = tid >> 5, lane = tid & 31;
    const int bm = blockIdx.y * 128, bn = blockIdx.x * 128;
    const int wm = wid >> 2, wn = wid & 3;      // 2 x 4 warps

    float acc[4][NT][4];
    #pragma unroll
    for (int i = 0; i < 4; i++)
        #pragma unroll
        for (int j = 0; j < NT; j++)
            #pragma unroll
            for (int v = 0; v < 4; v++) acc[i][j][v] = 0.0f;

    const int nIter = K >> 6;

    auto load_stage = [&](int i) {
        const uint32_t s0 = sb + (i % 3) * STG;
        const int k0 = i << 6;
        #pragma unroll
        for (int o = 0; o < 4; o++) {                   // A: 128 rows x 8 chunks
            int idx = tid + o * 256;
            int r = idx >> 3, c = idx & 7;
            uint32_t soff = (uint32_t)(r * 128 + ((c ^ (r & 7)) << 4));
            cpasync16(s0 + soff, A + (size_t)(bm + r) * K + k0 + c * 8);
        }
        #pragma unroll
        for (int o = 0; o < 4; o++) {                   // B: 128 rows x 8 chunks
            int idx = tid + o * 256;
            int r = idx >> 3, c = idx & 7;
            cpasync16(s0 + ASTG + (uint32_t)(r * 128 + ((c ^ (r & 7)) << 4)),
                      Br + (size_t)(bn + r) * K + k0 + c * 8);
        }
        cp_commit();
    };

    // per-thread ldmatrix row/group decomposition (validated layout)
    const int g  = lane >> 3;
    const int glr = lane & 7;
    const int arow = (g & 1) * 8 + glr;   // A x4: rows pair then chunk pair
    const int ach  = g >> 1;
    const int brow = (g >> 1) * 8 + glr;  // B x4: chunk pair then rows pair
    const int bch  = g & 1;

    load_stage(0);
    load_stage(1);

    for (int i = 0; i < nIter; ++i) {
        if (i + 1 < nIter) cp_wait1();      // stage i arrived (i+1 may be in flight)
        else               cp_wait0();
        __syncthreads();                    // slot (i-1)%3 now free for reuse
        if (i + 2 < nIter) load_stage(i + 2);

        const uint32_t s0 = sb + (i % 3) * STG;
        #pragma unroll
        for (int ks = 0; ks < 4; ks++) {
            const int c0 = ks * 2;
            uint32_t bf[NT][2];
            #pragma unroll
            for (int nt2 = 0; nt2 < NT / 2; nt2++) {
                int row = wn * 32 + nt2 * 16 + brow;
                uint32_t addr = s0 + ASTG + row * 128 + (((c0 + bch) ^ (row & 7)) << 4);
                LDSM_X4(bf[2*nt2][0], bf[2*nt2][1], bf[2*nt2+1][0], bf[2*nt2+1][1], addr);
            }
            uint32_t af[4][4];
            #pragma unroll
            for (int mt = 0; mt < 4; mt++) {
                int row = wm * 64 + mt * 16 + arow;
                uint32_t addr = s0 + row * 128 + (((c0 + ach) ^ (row & 7)) << 4);
                LDSM_X4(af[mt][0], af[mt][1], af[mt][2], af[mt][3], addr);
            }
            #pragma unroll
            for (int mt = 0; mt < 4; mt++)
                #pragma unroll
                for (int nt = 0; nt < NT; nt++)
                    MMA16816(acc[mt][nt], af[mt][0], af[mt][1], af[mt][2], af[mt][3],
                             bf[nt][0], bf[nt][1]);
        }
    }
    __syncthreads();

    // ---- epilogue ----
    const float ws = g_scales[sIdx];
    const int qr = lane >> 2;
    const int qc = (lane & 3) * 2;

    if (!FUSED) {
        #pragma unroll
        for (int mt = 0; mt < 4; mt++) {
            #pragma unroll
            for (int nt = 0; nt < NT; nt++) {
                int col = bn + wn * 32 + nt * 8 + qc;
                float bs0 = __ldg(&bias[col]), bs1 = __ldg(&bias[col + 1]);
                #pragma unroll
                for (int h = 0; h < 2; h++) {
                    size_t row = (size_t)(bm + wm * 64 + mt * 16 + qr + h * 8);
                    float o0 = fmaf(acc[mt][nt][2*h + 0], ws, bs0);
                    float o1 = fmaf(acc[mt][nt][2*h + 1], ws, bs1);
                    __nv_bfloat162 p;
                    p.x = __float2bfloat16(fmaxf(o0, 0.0f));
                    p.y = __float2bfloat16(fmaxf(o1, 0.0f));
                    *reinterpret_cast<__nv_bfloat162*>(oH + row * Nd + col) = p;
                }
            }
        }
    } else {
        // stage scaled net rows into smem: snet[128][128] (64 KB <= 96 KB pipeline smem)
        float* snet = reinterpret_cast<float*>(smem);
        #pragma unroll
        for (int mt = 0; mt < 4; mt++) {
            #pragma unroll
            for (int nt = 0; nt < NT; nt++) {
                int col = wn * 32 + nt * 8 + qc;
                float bs0 = __ldg(&bias[col]), bs1 = __ldg(&bias[col + 1]);
                #pragma unroll
                for (int h = 0; h < 2; h++) {
                    int row = wm * 64 + mt * 16 + qr + h * 8;
                    snet[row * 128 + col]     = fmaf(acc[mt][nt][2*h + 0], ws, bs0);
                    snet[row * 128 + col + 1] = fmaf(acc[mt][nt][2*h + 1], ws, bs1);
                }
            }
        }
        __syncthreads();
        // distribution: each of 8 warps handles 16 rows
        #pragma unroll
        for (int rr = 0; rr < 16; rr++) {
            int row = wid * 16 + rr;
            size_t grow = (size_t)(bm + row);
            float s = 0.0f;
            #pragma unroll
            for (int h = 0; h < 2; h++) {
                int j = lane + h * 32;
                float mu = snet[row * 128 + j];
                float ls = fminf(fmaxf(snet[row * 128 + ACT + j], -20.0f), 2.0f);
                float sd = expf(ls);
                float e  = eps[grow * ACT + j];
                float pi = fmaf(sd, e, mu);
                outAction[grow * ACT + j] = tanhf(pi);
                float z  = (pi - mu) / sd;
                float m2p = -2.0f * pi;
                float sp  = fmaxf(m2p, 0.0f) + log1pf(expf(-fabsf(m2p)));  // softplus(-2*pi)
                s += -0.5f*z*z - ls - 0.91893853320467274f
                     - 2.0f*(0.69314718055994531f - pi - sp);
            }
            #pragma unroll
            for (int o = 16; o; o >>= 1) s += __shfl_xor_sync(0xffffffffu, s, o);
            if (lane == 0 && outLogp) outLogp[grow] = s;
        }
    }
}

// ---------------- launcher ----------------
extern "C" void kernel_launch(void* const* d_in, const int* in_sizes, int n_in,
                              void* d_out, int out_size) {
    const float* obs = (const float*)d_in[0];
    const float* eps = (const float*)d_in[1];
    const float* W1  = (const float*)d_in[2];
    const float* b1  = (const float*)d_in[3];
    const float* W2  = (const float*)d_in[4];
    const float* b2  = (const float*)d_in[5];
    const float* W3  = (const float*)d_in[6];
    const float* b3  = (const float*)d_in[7];

    float* out = (float*)d_out;
    float* outAction = out;
    float* outLogp = (out_size >= B_ROWS*(ACT+1)) ? (out + (size_t)B_ROWS*ACT) : nullptr;

    const float S_IN = (float)(1.0/12000.0);

    __nv_bfloat16 *pW1r, *pW2r, *pW3r, *px, *ph1, *ph2;
    float *pb1q, *pb2q, *pb3q;
    cudaGetSymbolAddress((void**)&pW1r, g_W1r);
    cudaGetSymbolAddress((void**)&pW2r, g_W2r);
    cudaGetSymbolAddress((void**)&pW3r, g_W3r);
    cudaGetSymbolAddress((void**)&pb1q, g_b1q);
    cudaGetSymbolAddress((void**)&pb2q, g_b2q);
    cudaGetSymbolAddress((void**)&pb3q, g_b3q);
    cudaGetSymbolAddress((void**)&px,  g_x);
    cudaGetSymbolAddress((void**)&ph1, g_h1);
    cudaGetSymbolAddress((void**)&ph2, g_h2);

    const int SMEM = 3 * STG;   // 98304; 2 CTAs/SM = 192 KB <= 228 KB
    cudaFuncSetAttribute(gemm_mma<false>, cudaFuncAttributeMaxDynamicSharedMemorySize, SMEM);
    cudaFuncSetAttribute(gemm_mma<true>,  cudaFuncAttributeMaxDynamicSharedMemorySize, SMEM);

    // 1) quantization prep (maxbits accumulates idempotently across replays)
    maxabs3_kernel<<<416, 256>>>(W1, W2, W3);
    quant_all_kernel<<<512, 256>>>(W1, b1, W2, b2, W3, b3, S_IN);

    // 2) input conversion
    conv_x_kernel<<<1024, 256>>>(obs);

    // 3) MLP on tensor cores (register HMMA, 128x128 tiles, 2 CTAs/SM)
    dim3 g1(H1D/128, B_ROWS/128);
    gemm_mma<false><<<g1, 256, SMEM>>>(px, pW1r, pb1q, OBS, H1D, 0, ph1,
                                       nullptr, nullptr, nullptr);
    dim3 g2(H2D/128, B_ROWS/128);
    gemm_mma<false><<<g2, 256, SMEM>>>(ph1, pW2r, pb2q, H1D, H2D, 1, ph2,
                                       nullptr, nullptr, nullptr);
    dim3 g3(1, B_ROWS/128);
    gemm_mma<true><<<g3, 256, SMEM>>>(ph2, pW3r, pb3q, H2D, NOUT, 2, nullptr,
                                      eps, outAction, outLogp);
}

// round 12
// speedup vs baseline: 1.2021x; 1.0496x over previous
#include <cuda_runtime.h>
#include <cuda_bf16.h>
#include <math.h>
#include <stdint.h>

#define B_ROWS 32768
#define OBS    512
#define H1D    1024
#define H2D    1024
#define ACT    64
#define NOUT   (2*ACT)

// ---------------- device scratch (static: no allocations allowed) ----------------
__device__ __nv_bfloat16 g_W1r[H1D*OBS];     // integer-valued bf16 weights (exact)
__device__ __nv_bfloat16 g_W2r[H2D*H1D];
__device__ __nv_bfloat16 g_W3r[NOUT*H2D];
__device__ float g_b1q[H1D];
__device__ float g_b2q[H2D];
__device__ float g_b3q[NOUT];
__device__ float g_scales[3];
__device__ unsigned g_maxbits[3] = {0u, 0u, 0u};   // atomicMax over identical data: idempotent
__device__ __nv_bfloat16 g_x[(size_t)B_ROWS*OBS];
__device__ __nv_bfloat16 g_h1[(size_t)B_ROWS*H1D];
__device__ __nv_bfloat16 g_h2[(size_t)B_ROWS*H2D];

// ---------------- PTX helpers (sm_103-safe subset only) ----------------
__device__ __forceinline__ uint32_t smem_u32(const void* p) {
    uint32_t a;
    asm("{ .reg .u64 t; cvta.to.shared.u64 t, %1; cvt.u32.u64 %0, t; }" : "=r"(a) : "l"(p));
    return a;
}
__device__ __forceinline__ void cpasync16(uint32_t dst, const void* src) {
    asm volatile("cp.async.cg.shared.global [%0], [%1], 16;" :: "r"(dst), "l"(src));
}
__device__ __forceinline__ void cp_commit() { asm volatile("cp.async.commit_group;" ::: "memory"); }
__device__ __forceinline__ void cp_wait1()  { asm volatile("cp.async.wait_group 1;" ::: "memory"); }
__device__ __forceinline__ void cp_wait0()  { asm volatile("cp.async.wait_group 0;" ::: "memory"); }

#define LDSM_X4(r0, r1, r2, r3, addr)                                          \
    asm volatile("ldmatrix.sync.aligned.m8n8.x4.shared.b16 {%0,%1,%2,%3}, [%4];" \
        : "=r"(r0), "=r"(r1), "=r"(r2), "=r"(r3) : "r"(addr))

#define MMA16816(c, a0, a1, a2, a3, b0, b1)                                    \
    asm volatile("mma.sync.aligned.m16n8k16.row.col.f32.bf16.bf16.f32 "        \
        "{%0,%1,%2,%3}, {%4,%5,%6,%7}, {%8,%9}, {%0,%1,%2,%3};"                \
        : "+f"((c)[0]), "+f"((c)[1]), "+f"((c)[2]), "+f"((c)[3])               \
        : "r"(a0), "r"(a1), "r"(a2), "r"(a3), "r"(b0), "r"(b1))

__device__ __forceinline__ float ex2f(float x) {
    float r; asm("ex2.approx.f32 %0, %1;" : "=f"(r) : "f"(x)); return r;
}
__device__ __forceinline__ float lg2f(float x) {
    float r; asm("lg2.approx.f32 %0, %1;" : "=f"(r) : "f"(x)); return r;
}
__device__ __forceinline__ float tanhapx(float x) {
    float r; asm("tanh.approx.f32 %0, %1;" : "=f"(r) : "f"(x)); return r;
}

// ---------------- quantization prep ----------------
// fused 3-tensor max|W|: blocks [0,128)->W1, [128,384)->W2, [384,416)->W3
__global__ void maxabs3_kernel(const float* __restrict__ W1, const float* __restrict__ W2,
                               const float* __restrict__ W3) {
    const float* W; int n, slot, idx, nb;
    int b = blockIdx.x;
    if (b < 128)      { W = W1; n = H1D*OBS;  slot = 0; idx = b;       nb = 128; }
    else if (b < 384) { W = W2; n = H2D*H1D;  slot = 1; idx = b - 128; nb = 256; }
    else              { W = W3; n = NOUT*H2D; slot = 2; idx = b - 384; nb = 32;  }
    unsigned m = 0u;
    for (int i = idx*blockDim.x + threadIdx.x; i < n; i += nb*blockDim.x)
        m = max(m, __float_as_uint(fabsf(W[i])));
    #pragma unroll
    for (int o = 16; o; o >>= 1) m = max(m, __shfl_xor_sync(0xffffffffu, m, o));
    __shared__ unsigned sm[32];
    int lane = threadIdx.x & 31, wid = threadIdx.x >> 5;
    if (lane == 0) sm[wid] = m;
    __syncthreads();
    if (wid == 0) {
        m = (lane < (int)(blockDim.x >> 5)) ? sm[lane] : 0u;
        #pragma unroll
        for (int o = 16; o; o >>= 1) m = max(m, __shfl_xor_sync(0xffffffffu, m, o));
        if (lane == 0) atomicMax(&g_maxbits[slot], m);
    }
}

__device__ __forceinline__ float qwr(float w, float rs) {   // integer part (mult by recip; damped)
    float r = rintf(w * rs);
    return fminf(fmaxf(r, -127.0f), 127.0f);
}
__device__ __forceinline__ float qb(float b, float s, float rs) {
    float r = rintf(b * rs);
    r = fminf(fmaxf(r, -128.0f), 127.0f);
    return r * s;
}

__global__ void quant_all_kernel(const float* __restrict__ W1, const float* __restrict__ b1,
                                 const float* __restrict__ W2, const float* __restrict__ b2,
                                 const float* __restrict__ W3, const float* __restrict__ b3,
                                 float s_in) {
    const float ws1 = __fdiv_rn(__uint_as_float(g_maxbits[0]), 127.0f);
    const float ws2 = __fdiv_rn(__uint_as_float(g_maxbits[1]), 127.0f);
    const float ws3 = __fdiv_rn(__uint_as_float(g_maxbits[2]), 127.0f);
    const float rs1 = 1.0f / ws1, rs2 = 1.0f / ws2, rs3 = 1.0f / ws3;
    const float sb1 = s_in * ws1;
    const float sb2 = sb1 * ws2;
    const float sb3 = sb2 * ws3;
    const int tid = blockIdx.x*blockDim.x + threadIdx.x;
    const int stride = gridDim.x*blockDim.x;
    if (tid == 0) { g_scales[0] = ws1; g_scales[1] = ws2; g_scales[2] = ws3; }
    for (int i = tid; i < H1D*OBS/2; i += stride) {
        float2 v = ((const float2*)W1)[i];
        __nv_bfloat162 p;
        p.x = __float2bfloat16(qwr(v.x, rs1)); p.y = __float2bfloat16(qwr(v.y, rs1));
        ((__nv_bfloat162*)g_W1r)[i] = p;
    }
    for (int i = tid; i < H2D*H1D/2; i += stride) {
        float2 v = ((const float2*)W2)[i];
        __nv_bfloat162 p;
        p.x = __float2bfloat16(qwr(v.x, rs2)); p.y = __float2bfloat16(qwr(v.y, rs2));
        ((__nv_bfloat162*)g_W2r)[i] = p;
    }
    for (int i = tid; i < NOUT*H2D/2; i += stride) {
        float2 v = ((const float2*)W3)[i];
        __nv_bfloat162 p;
        p.x = __float2bfloat16(qwr(v.x, rs3)); p.y = __float2bfloat16(qwr(v.y, rs3));
        ((__nv_bfloat162*)g_W3r)[i] = p;
    }
    for (int i = tid; i < H1D;  i += stride) g_b1q[i] = qb(b1[i], sb1, 1.0f/sb1);
    for (int i = tid; i < H2D;  i += stride) g_b2q[i] = qb(b2[i], sb2, 1.0f/sb2);
    for (int i = tid; i < NOUT; i += stride) g_b3q[i] = qb(b3[i], sb3, 1.0f/sb3);
}

// ---------------- input conversion: x = obs * s_in^2 as bf16 (float4 -> bf16x4) ----------------
__global__ void conv_x_kernel(const float* __restrict__ obs) {
    const float F0 = (float)((1.0/12000.0) * (1.0/12000.0));
    const size_t n4 = (size_t)B_ROWS * OBS / 4;
    for (size_t i = (size_t)blockIdx.x*blockDim.x + threadIdx.x; i < n4;
         i += (size_t)gridDim.x*blockDim.x) {
        float4 v = ((const float4*)obs)[i];
        __nv_bfloat162 p0, p1;
        p0.x = __float2bfloat16(v.x * F0); p0.y = __float2bfloat16(v.y * F0);
        p1.x = __float2bfloat16(v.z * F0); p1.y = __float2bfloat16(v.w * F0);
        uint2 o; o.x = *(uint32_t*)&p0; o.y = *(uint32_t*)&p1;
        ((uint2*)g_x)[i] = o;
    }
}

// ---------------- HMMA GEMM, 128x128 CTA tile, 2 CTAs/SM (validated R10 core) ----------------
#define BK 64
#define ASTG (128*BK*2)          // 16 KB A per stage
#define BSTG (128*BK*2)          // 16 KB B per stage (NTILE=128)
#define STG  (ASTG + BSTG)       // 32 KB per stage; 3 stages = 96 KB

template<bool FUSED>
__global__ __launch_bounds__(256, 2)
void gemm_mma(const __nv_bfloat16* __restrict__ A,
              const __nv_bfloat16* __restrict__ Br,  const float* __restrict__ bias,
              int K, int Nd, int sIdx,
              __nv_bfloat16* __restrict__ oH,
              const float* __restrict__ eps,
              float* __restrict__ outAction, float* __restrict__ outLogp) {
    constexpr int NT = 4;                       // n-subtiles per warp (32 cols)
    extern __shared__ __align__(128) char smem[];
    const uint32_t sb = smem_u32(smem);
    const int tid = threadIdx.x, wid = tid >> 5, lane = tid & 31;
    const int bm = blockIdx.y * 128, bn = blockIdx.x * 128;
    const int wm = wid >> 2, wn = wid & 3;      // 2 x 4 warps

    float acc[4][NT][4];
    #pragma unroll
    for (int i = 0; i < 4; i++)
        #pragma unroll
        for (int j = 0; j < NT; j++)
            #pragma unroll
            for (int v = 0; v < 4; v++) acc[i][j][v] = 0.0f;

    const int nIter = K >> 6;

    auto load_stage = [&](int i) {
        const uint32_t s0 = sb + (i % 3) * STG;
        const int k0 = i << 6;
        #pragma unroll
        for (int o = 0; o < 4; o++) {                   // A: 128 rows x 8 chunks
            int idx = tid + o * 256;
            int r = idx >> 3, c = idx & 7;
            uint32_t soff = (uint32_t)(r * 128 + ((c ^ (r & 7)) << 4));
            cpasync16(s0 + soff, A + (size_t)(bm + r) * K + k0 + c * 8);
        }
        #pragma unroll
        for (int o = 0; o < 4; o++) {                   // B: 128 rows x 8 chunks
            int idx = tid + o * 256;
            int r = idx >> 3, c = idx & 7;
            cpasync16(s0 + ASTG + (uint32_t)(r * 128 + ((c ^ (r & 7)) << 4)),
                      Br + (size_t)(bn + r) * K + k0 + c * 8);
        }
        cp_commit();
    };

    // per-thread ldmatrix row/group decomposition (validated layout)
    const int g  = lane >> 3;
    const int glr = lane & 7;
    const int arow = (g & 1) * 8 + glr;   // A x4: rows pair then chunk pair
    const int ach  = g >> 1;
    const int brow = (g >> 1) * 8 + glr;  // B x4: chunk pair then rows pair
    const int bch  = g & 1;

    load_stage(0);
    load_stage(1);

    for (int i = 0; i < nIter; ++i) {
        if (i + 1 < nIter) cp_wait1();      // stage i arrived (i+1 may be in flight)
        else               cp_wait0();
        __syncthreads();                    // slot (i-1)%3 now free for reuse
        if (i + 2 < nIter) load_stage(i + 2);

        const uint32_t s0 = sb + (i % 3) * STG;
        #pragma unroll
        for (int ks = 0; ks < 4; ks++) {
            const int c0 = ks * 2;
            uint32_t bf[NT][2];
            #pragma unroll
            for (int nt2 = 0; nt2 < NT / 2; nt2++) {
                int row = wn * 32 + nt2 * 16 + brow;
                uint32_t addr = s0 + ASTG + row * 128 + (((c0 + bch) ^ (row & 7)) << 4);
                LDSM_X4(bf[2*nt2][0], bf[2*nt2][1], bf[2*nt2+1][0], bf[2*nt2+1][1], addr);
            }
            uint32_t af[4][4];
            #pragma unroll
            for (int mt = 0; mt < 4; mt++) {
                int row = wm * 64 + mt * 16 + arow;
                uint32_t addr = s0 + row * 128 + (((c0 + ach) ^ (row & 7)) << 4);
                LDSM_X4(af[mt][0], af[mt][1], af[mt][2], af[mt][3], addr);
            }
            #pragma unroll
            for (int mt = 0; mt < 4; mt++)
                #pragma unroll
                for (int nt = 0; nt < NT; nt++)
                    MMA16816(acc[mt][nt], af[mt][0], af[mt][1], af[mt][2], af[mt][3],
                             bf[nt][0], bf[nt][1]);
        }
    }
    __syncthreads();

    // ---- epilogue ----
    const float ws = g_scales[sIdx];
    const int qr = lane >> 2;
    const int qc = (lane & 3) * 2;

    if (!FUSED) {
        #pragma unroll
        for (int mt = 0; mt < 4; mt++) {
            #pragma unroll
            for (int nt = 0; nt < NT; nt++) {
                int col = bn + wn * 32 + nt * 8 + qc;
                float bs0 = __ldg(&bias[col]), bs1 = __ldg(&bias[col + 1]);
                #pragma unroll
                for (int h = 0; h < 2; h++) {
                    size_t row = (size_t)(bm + wm * 64 + mt * 16 + qr + h * 8);
                    float o0 = fmaf(acc[mt][nt][2*h + 0], ws, bs0);
                    float o1 = fmaf(acc[mt][nt][2*h + 1], ws, bs1);
                    __nv_bfloat162 p;
                    p.x = __float2bfloat16(fmaxf(o0, 0.0f));
                    p.y = __float2bfloat16(fmaxf(o1, 0.0f));
                    *reinterpret_cast<__nv_bfloat162*>(oH + row * Nd + col) = p;
                }
            }
        }
    } else {
        // stage scaled net rows into smem: snet[128][128] (64 KB <= 96 KB pipeline smem)
        float* snet = reinterpret_cast<float*>(smem);
        #pragma unroll
        for (int mt = 0; mt < 4; mt++) {
            #pragma unroll
            for (int nt = 0; nt < NT; nt++) {
                int col = wn * 32 + nt * 8 + qc;
                float bs0 = __ldg(&bias[col]), bs1 = __ldg(&bias[col + 1]);
                #pragma unroll
                for (int h = 0; h < 2; h++) {
                    int row = wm * 64 + mt * 16 + qr + h * 8;
                    snet[row * 128 + col]     = fmaf(acc[mt][nt][2*h + 0], ws, bs0);
                    snet[row * 128 + col + 1] = fmaf(acc[mt][nt][2*h + 1], ws, bs1);
                }
            }
        }
        __syncthreads();
        // distribution epilogue, MUFU-minimized:
        // logp = sum(-0.5 e^2 - ls + 2|pi|) - 64*0.5*log(2pi) - 128*log2 + 2*ln2*log2(prod(1+E))
        //   where E = e^{-2|pi|}; each (1+E) in (1,2] so prod over 64 <= 2^64 fits fp32.
        const float L2E = 1.44269504088896f;       // log2(e)
        const float NL2E2 = -2.88539008177793f;    // -2*log2(e)
        const float LN2 = 0.69314718055994531f;
        const float CROW = -64.0f * 0.91893853320467274f - 128.0f * LN2;
        #pragma unroll
        for (int rr = 0; rr < 16; rr++) {
            int row = wid * 16 + rr;
            size_t grow = (size_t)(bm + row);
            float s = 0.0f, P = 1.0f;
            #pragma unroll
            for (int h = 0; h < 2; h++) {
                int j = lane + h * 32;
                float mu = snet[row * 128 + j];
                float ls = fminf(fmaxf(snet[row * 128 + ACT + j], -20.0f), 2.0f);
                float sd = ex2f(ls * L2E);                  // exp(ls)
                float e  = eps[grow * ACT + j];
                float pi = fmaf(sd, e, mu);
                outAction[grow * ACT + j] = tanhapx(pi);
                float api = fabsf(pi);
                float E = ex2f(api * NL2E2);                // e^{-2|pi|}
                P *= (1.0f + E);
                s += fmaf(-0.5f * e, e, 2.0f * api - ls);
            }
            #pragma unroll
            for (int o = 16; o; o >>= 1) {
                s += __shfl_xor_sync(0xffffffffu, s, o);
                P *= __shfl_xor_sync(0xffffffffu, P, o);
            }
            if (lane == 0 && outLogp)
                outLogp[grow] = s + CROW + 2.0f * LN2 * lg2f(P);
        }
    }
}

// ---------------- launcher ----------------
extern "C" void kernel_launch(void* const* d_in, const int* in_sizes, int n_in,
                              void* d_out, int out_size) {
    const float* obs = (const float*)d_in[0];
    const float* eps = (const float*)d_in[1];
    const float* W1  = (const float*)d_in[2];
    const float* b1  = (const float*)d_in[3];
    const float* W2  = (const float*)d_in[4];
    const float* b2  = (const float*)d_in[5];
    const float* W3  = (const float*)d_in[6];
    const float* b3  = (const float*)d_in[7];

    float* out = (float*)d_out;
    float* outAction = out;
    float* outLogp = (out_size >= B_ROWS*(ACT+1)) ? (out + (size_t)B_ROWS*ACT) : nullptr;

    const float S_IN = (float)(1.0/12000.0);

    __nv_bfloat16 *pW1r, *pW2r, *pW3r, *px, *ph1, *ph2;
    float *pb1q, *pb2q, *pb3q;
    cudaGetSymbolAddress((void**)&pW1r, g_W1r);
    cudaGetSymbolAddress((void**)&pW2r, g_W2r);
    cudaGetSymbolAddress((void**)&pW3r, g_W3r);
    cudaGetSymbolAddress((void**)&pb1q, g_b1q);
    cudaGetSymbolAddress((void**)&pb2q, g_b2q);
    cudaGetSymbolAddress((void**)&pb3q, g_b3q);
    cudaGetSymbolAddress((void**)&px,  g_x);
    cudaGetSymbolAddress((void**)&ph1, g_h1);
    cudaGetSymbolAddress((void**)&ph2, g_h2);

    const int SMEM = 3 * STG;   // 98304; 2 CTAs/SM = 192 KB <= 228 KB
    cudaFuncSetAttribute(gemm_mma<false>, cudaFuncAttributeMaxDynamicSharedMemorySize, SMEM);
    cudaFuncSetAttribute(gemm_mma<true>,  cudaFuncAttributeMaxDynamicSharedMemorySize, SMEM);

    // 1) quantization prep (maxbits accumulates idempotently across replays)
    maxabs3_kernel<<<416, 256>>>(W1, W2, W3);
    quant_all_kernel<<<512, 256>>>(W1, b1, W2, b2, W3, b3, S_IN);

    // 2) input conversion
    conv_x_kernel<<<1024, 256>>>(obs);

    // 3) MLP on tensor cores (register HMMA, 128x128 tiles, 2 CTAs/SM)
    dim3 g1(H1D/128, B_ROWS/128);
    gemm_mma<false><<<g1, 256, SMEM>>>(px, pW1r, pb1q, OBS, H1D, 0, ph1,
                                       nullptr, nullptr, nullptr);
    dim3 g2(H2D/128, B_ROWS/128);
    gemm_mma<false><<<g2, 256, SMEM>>>(ph1, pW2r, pb2q, H1D, H2D, 1, ph2,
                                       nullptr, nullptr, nullptr);
    dim3 g3(1, B_ROWS/128);
    gemm_mma<true><<<g3, 256, SMEM>>>(ph2, pW3r, pb3q, H2D, NOUT, 2, nullptr,
                                      eps, outAction, outLogp);
}